// round 3
// baseline (speedup 1.0000x reference)
#include <cuda_runtime.h>
#include <cuda_bf16.h>
#include <math_constants.h>

// Fully collapsed model:
//   out[b,n,e] = cd[b,n]*u[e] + density[b,n]*v[e] + c[e]
//   u = W_dist @ W_out[0:42], v = W_den @ W_out[84:126],
//   c = b_dist@W_out[0:42] + emb[49]@W_out[42:84] + b_den@W_out[84:126] + b_out
//
// Single fused kernel: block 0 computes u/v/c and publishes via g_flag;
// all other work (point load, centroid, 3-NN) overlaps the precompute;
// blocks acquire the flag only right before the output epilogue.

__device__ float g_u[128];
__device__ float g_v[128];
__device__ float g_c[128];
__device__ unsigned g_flag = 0;   // set by block 0 when u/v/c are ready
__device__ unsigned g_done = 0;   // completion counter; last block resets both

#define D3   42
#define NPT  49
#define EOUT 128
#define BPB  4
#define ROWS (BPB * NPT)          // 196 point-rows per block

__global__ __launch_bounds__(256)
void nrpf_fused(const float* __restrict__ points,
                const float* __restrict__ W_dist,
                const float* __restrict__ b_dist,
                const float* __restrict__ emb,
                const float* __restrict__ W_den,
                const float* __restrict__ b_den,
                const float* __restrict__ W_out,
                const float* __restrict__ b_out,
                float* __restrict__ out,
                int nrows_total) {
    const int t   = threadIdx.x;
    const int bid = blockIdx.x;

    __shared__ float4 s_raw4[(ROWS * 3 + 3) / 4];   // 147 float4 staging
    __shared__ float4 s_pq[ROWS];                   // {x, y, z, |p|^2}
    __shared__ float2 s_cddn[ROWS];                 // {centroid_dist, density}
    __shared__ float  s_cent[BPB * 3];

    // ---- block 0: compute u/v/c, publish ----
    if (bid == 0) {
        if (t < EOUT) {
            const int e = t;
            float u = 0.f, v = 0.f, c = 0.f;
#pragma unroll
            for (int d = 0; d < D3; d++) {
                float wo0 = W_out[d * EOUT + e];
                float wo1 = W_out[(D3 + d) * EOUT + e];
                float wo2 = W_out[(2 * D3 + d) * EOUT + e];
                u = fmaf(W_dist[d], wo0, u);
                v = fmaf(W_den[d], wo2, v);
                c = fmaf(b_dist[d], wo0, c);
                c = fmaf(emb[NPT * D3 + d], wo1, c);
                c = fmaf(b_den[d], wo2, c);
            }
            g_u[e] = u;
            g_v[e] = v;
            g_c[e] = c + b_out[e];
            __threadfence();
        }
        __syncthreads();
        if (t == 0) atomicExch(&g_flag, 1u);
    }

    // ---- load this block's points (4 batches = 588 floats, coalesced float4) ----
    const int   row0      = bid * ROWS;
    int         rows_here = nrows_total - row0;
    if (rows_here > ROWS) rows_here = ROWS;
    const float* pbase = points + (size_t)row0 * 3;
    float* s_raw = reinterpret_cast<float*>(s_raw4);

    if (rows_here == ROWS) {
        if (t < (ROWS * 3) / 4)
            s_raw4[t] = reinterpret_cast<const float4*>(pbase)[t];
    } else {
        for (int j = t; j < rows_here * 3; j += 256) s_raw[j] = pbase[j];
    }
    __syncthreads();

    // ---- build float4 point table with packed squared norm ----
    if (t < rows_here) {
        float x = s_raw[t * 3 + 0];
        float y = s_raw[t * 3 + 1];
        float z = s_raw[t * 3 + 2];
        float n2 = fmaf(x, x, fmaf(y, y, z * z));
        s_pq[t] = make_float4(x, y, z, n2);
    }
    __syncthreads();

    // ---- centroids: 3 threads per batch slot ----
    if (t < BPB * 3) {
        int gg = t / 3, dim = t % 3;
        if (gg * NPT < rows_here) {
            const float* p = reinterpret_cast<const float*>(s_pq + gg * NPT);
            float s = 0.f;
#pragma unroll 7
            for (int n = 0; n < NPT; n++) s += p[n * 4 + dim];
            s_cent[t] = s * (1.0f / 49.0f);
        }
    }
    __syncthreads();

    // ---- per point: centroid distance + mean of 3 nearest distances ----
    if (t < rows_here) {
        const int g = t / 49;
        const int l = t - g * 49;
        const float4 me = s_pq[t];
        const float4* pq = s_pq + g * NPT;

        float dx = me.x - s_cent[g * 3 + 0];
        float dy = me.y - s_cent[g * 3 + 1];
        float dz = me.z - s_cent[g * 3 + 2];
        float cd = sqrtf(fmaf(dx, dx, fmaf(dy, dy, dz * dz)));

        float m0 = CUDART_INF_F, m1 = CUDART_INF_F, m2 = CUDART_INF_F;
#pragma unroll
        for (int m = 0; m < NPT; m++) {
            float4 q = pq[m];                       // broadcast LDS.128
            float dot = fmaf(me.x, q.x, fmaf(me.y, q.y, me.z * q.z));
            float d2  = fmaf(-2.f, dot, me.w + q.w);
            d2 = fmaxf(d2, 0.f);
            d2 = (m == l) ? CUDART_INF_F : d2;      // mask self
            // 3-min insertion network (FMNMX only)
            float b0 = fmaxf(m0, d2);
            m0 = fminf(m0, d2);
            float b1 = fmaxf(m1, b0);
            m1 = fminf(m1, b0);
            m2 = fminf(m2, b1);
        }
        float dn = (sqrtf(m0) + sqrtf(m1) + sqrtf(m2)) * (1.0f / 3.0f);
        s_cddn[t] = make_float2(cd, dn);
    }
    __syncthreads();

    // ---- acquire u/v/c (overlapped with everything above) ----
    if (bid != 0) {
        if (t == 0) {
            while (atomicAdd(&g_flag, 0u) == 0u) { __nanosleep(64); }
            __threadfence();
        }
        __syncthreads();
    }

    const int q = t & 31;
    const float4 ru = reinterpret_cast<const float4*>(g_u)[q];
    const float4 rv = reinterpret_cast<const float4*>(g_v)[q];
    const float4 rc = reinterpret_cast<const float4*>(g_c)[q];

    // ---- epilogue: out[row, :] = cd*u + dn*v + c ; STG.128 coalesced ----
    const int w = t >> 5;
    float4* outp = reinterpret_cast<float4*>(out) + (size_t)row0 * 32 + q;
#pragma unroll 4
    for (int r = w; r < rows_here; r += 8) {
        float2 cddn = s_cddn[r];                    // broadcast LDS.64
        float4 o;
        o.x = fmaf(cddn.x, ru.x, fmaf(cddn.y, rv.x, rc.x));
        o.y = fmaf(cddn.x, ru.y, fmaf(cddn.y, rv.y, rc.y));
        o.z = fmaf(cddn.x, ru.z, fmaf(cddn.y, rv.z, rc.z));
        o.w = fmaf(cddn.x, ru.w, fmaf(cddn.y, rv.w, rc.w));
        outp[(size_t)r * 32] = o;
    }

    // ---- reset flags for the next graph replay (last block only) ----
    __syncthreads();
    if (t == 0) {
        unsigned d = atomicAdd(&g_done, 1u);
        if (d == gridDim.x - 1) {
            g_done = 0u;
            g_flag = 0u;
        }
    }
}

extern "C" void kernel_launch(void* const* d_in, const int* in_sizes, int n_in,
                              void* d_out, int out_size) {
    const float* points = (const float*)d_in[0];
    const float* W_dist = (const float*)d_in[1];
    const float* b_dist = (const float*)d_in[2];
    const float* emb    = (const float*)d_in[3];
    const float* W_den  = (const float*)d_in[4];
    const float* b_den  = (const float*)d_in[5];
    const float* W_out  = (const float*)d_in[6];
    const float* b_out  = (const float*)d_in[7];
    float* out = (float*)d_out;

    int B = in_sizes[0] / (NPT * 3);
    int grid = (B + BPB - 1) / BPB;

    nrpf_fused<<<grid, 256>>>(points, W_dist, b_dist, emb, W_den, b_den,
                              W_out, b_out, out, B * NPT);
}

// round 4
// speedup vs baseline: 1.1369x; 1.1369x over previous
#include <cuda_runtime.h>
#include <cuda_bf16.h>
#include <math_constants.h>

// Collapsed model:
//   out[b,n,e] = cd[b,n]*u[e] + density[b,n]*v[e] + c[e]
// u/v/c precomputed from the tiny weight tensors by a 1-block kernel;
// the main kernel overlaps with it via programmatic dependent launch (PDL).

__device__ float g_u[128];
__device__ float g_v[128];
__device__ float g_c[128];

#define D3   42
#define NPT  49
#define EOUT 128
#define BPB  4
#define ROWS (BPB * NPT)          // 196 point-rows per block

// ---------------------------------------------------------------------------
// Precompute u/v/c: 1 block, 1024 threads, 8-way K-split + smem reduce.
// Triggers programmatic launch completion IMMEDIATELY so the main grid
// launches and runs its independent phases concurrently.
// ---------------------------------------------------------------------------
__global__ __launch_bounds__(1024)
void precompute_uvc(const float* __restrict__ W_dist,
                    const float* __restrict__ b_dist,
                    const float* __restrict__ emb,
                    const float* __restrict__ W_den,
                    const float* __restrict__ b_den,
                    const float* __restrict__ W_out,
                    const float* __restrict__ b_out) {
    cudaTriggerProgrammaticLaunchCompletion();

    __shared__ float su[8][128], sv[8][128], sc[8][128];
    int t = threadIdx.x;
    int e = t & 127;
    int s = t >> 7;          // 0..7
    float u = 0.f, v = 0.f, c = 0.f;
    for (int d = s; d < D3; d += 8) {
        float wo0 = W_out[d * EOUT + e];            // dist block
        float wo1 = W_out[(D3 + d) * EOUT + e];     // count block
        float wo2 = W_out[(2 * D3 + d) * EOUT + e]; // density block
        u = fmaf(W_dist[d], wo0, u);
        v = fmaf(W_den[d], wo2, v);
        c = fmaf(b_dist[d], wo0, c);
        c = fmaf(emb[NPT * D3 + d], wo1, c);
        c = fmaf(b_den[d], wo2, c);
    }
    su[s][e] = u; sv[s][e] = v; sc[s][e] = c;
    __syncthreads();
    if (s == 0) {
        float U = 0.f, V = 0.f, C = 0.f;
#pragma unroll
        for (int k = 0; k < 8; k++) { U += su[k][e]; V += sv[k][e]; C += sc[k][e]; }
        g_u[e] = U;
        g_v[e] = V;
        g_c[e] = C + b_out[e];
    }
}

// ---------------------------------------------------------------------------
// Main kernel: 4 batches per block, 256 threads. Launched with the PDL
// attribute; synchronizes on the precompute grid only after its own
// independent load/centroid phases.
// ---------------------------------------------------------------------------
__global__ __launch_bounds__(256)
void nrpf_main(const float* __restrict__ points, float* __restrict__ out,
               int nrows_total) {
    const int t   = threadIdx.x;
    const int bid = blockIdx.x;

    __shared__ float4 s_raw4[(ROWS * 3 + 3) / 4];   // 147 float4 staging
    __shared__ float4 s_pq[ROWS];                   // {x, y, z, |p|^2}
    __shared__ float2 s_cddn[ROWS];                 // {centroid_dist, density}
    __shared__ float  s_cent[BPB * 3];

    // ---- load this block's points (588 contiguous floats, float4) ----
    const int row0 = bid * ROWS;
    int rows_here  = nrows_total - row0;
    if (rows_here > ROWS) rows_here = ROWS;
    const float* pbase = points + (size_t)row0 * 3;
    float* s_raw = reinterpret_cast<float*>(s_raw4);

    if (rows_here == ROWS) {
        if (t < (ROWS * 3) / 4)
            s_raw4[t] = reinterpret_cast<const float4*>(pbase)[t];
    } else {
        for (int j = t; j < rows_here * 3; j += 256) s_raw[j] = pbase[j];
    }
    __syncthreads();

    // ---- build point table with packed squared norm ----
    if (t < rows_here) {
        float x = s_raw[t * 3 + 0];
        float y = s_raw[t * 3 + 1];
        float z = s_raw[t * 3 + 2];
        s_pq[t] = make_float4(x, y, z, fmaf(x, x, fmaf(y, y, z * z)));
    }
    __syncthreads();

    // ---- centroids: 3 threads per batch slot ----
    if (t < BPB * 3) {
        int gg = t / 3, dim = t % 3;
        if (gg * NPT < rows_here) {
            const float* p = reinterpret_cast<const float*>(s_pq + gg * NPT);
            float s = 0.f;
#pragma unroll 7
            for (int n = 0; n < NPT; n++) s += p[n * 4 + dim];
            s_cent[t] = s * (1.0f / 49.0f);
        }
    }

    // ---- wait for precompute grid, then issue u/v/c loads; their latency
    //      hides under the 3-NN compute below ----
    cudaGridDependencySynchronize();
    const int q = t & 31;
    const float4 ru = reinterpret_cast<const float4*>(g_u)[q];
    const float4 rv = reinterpret_cast<const float4*>(g_v)[q];
    const float4 rc = reinterpret_cast<const float4*>(g_c)[q];
    __syncthreads();

    // ---- per point: centroid distance + mean of 3 nearest distances ----
    if (t < rows_here) {
        const int g = t / 49;
        const int l = t - g * 49;
        const float4 me = s_pq[t];
        const float4* pq = s_pq + g * NPT;

        float dx = me.x - s_cent[g * 3 + 0];
        float dy = me.y - s_cent[g * 3 + 1];
        float dz = me.z - s_cent[g * 3 + 2];
        float cd = sqrtf(fmaf(dx, dx, fmaf(dy, dy, dz * dz)));

        float m0 = CUDART_INF_F, m1 = CUDART_INF_F, m2 = CUDART_INF_F;
#pragma unroll
        for (int m = 0; m < NPT; m++) {
            float4 p = pq[m];                       // broadcast LDS.128
            float dot = fmaf(me.x, p.x, fmaf(me.y, p.y, me.z * p.z));
            float d2  = fmaf(-2.f, dot, me.w + p.w);
            d2 = fmaxf(d2, 0.f);
            d2 = (m == l) ? CUDART_INF_F : d2;      // mask self
            // 3-min insertion network (FMNMX only)
            float b0 = fmaxf(m0, d2);
            m0 = fminf(m0, d2);
            float b1 = fmaxf(m1, b0);
            m1 = fminf(m1, b0);
            m2 = fminf(m2, b1);
        }
        float dn = (sqrtf(m0) + sqrtf(m1) + sqrtf(m2)) * (1.0f / 3.0f);
        s_cddn[t] = make_float2(cd, dn);
    }
    __syncthreads();

    // ---- epilogue: out[row, :] = cd*u + dn*v + c ; STG.128 coalesced ----
    const int w = t >> 5;
    float4* outp = reinterpret_cast<float4*>(out) + (size_t)row0 * 32 + q;
#pragma unroll 4
    for (int r = w; r < rows_here; r += 8) {
        float2 cddn = s_cddn[r];                    // broadcast LDS.64
        float4 o;
        o.x = fmaf(cddn.x, ru.x, fmaf(cddn.y, rv.x, rc.x));
        o.y = fmaf(cddn.x, ru.y, fmaf(cddn.y, rv.y, rc.y));
        o.z = fmaf(cddn.x, ru.z, fmaf(cddn.y, rv.z, rc.z));
        o.w = fmaf(cddn.x, ru.w, fmaf(cddn.y, rv.w, rc.w));
        outp[(size_t)r * 32] = o;
    }
}

extern "C" void kernel_launch(void* const* d_in, const int* in_sizes, int n_in,
                              void* d_out, int out_size) {
    const float* points = (const float*)d_in[0];
    const float* W_dist = (const float*)d_in[1];
    const float* b_dist = (const float*)d_in[2];
    const float* emb    = (const float*)d_in[3];
    const float* W_den  = (const float*)d_in[4];
    const float* b_den  = (const float*)d_in[5];
    const float* W_out  = (const float*)d_in[6];
    const float* b_out  = (const float*)d_in[7];
    float* out = (float*)d_out;

    int B = in_sizes[0] / (NPT * 3);
    int grid = (B + BPB - 1) / BPB;

    precompute_uvc<<<1, 1024>>>(W_dist, b_dist, emb, W_den, b_den, W_out, b_out);

    // Main kernel with programmatic dependent launch: overlaps with precompute,
    // ordering enforced by cudaGridDependencySynchronize() inside the kernel.
    cudaLaunchConfig_t cfg = {};
    cfg.gridDim  = dim3(grid, 1, 1);
    cfg.blockDim = dim3(256, 1, 1);
    cfg.dynamicSmemBytes = 0;
    cfg.stream = 0;
    cudaLaunchAttribute attrs[1];
    attrs[0].id = cudaLaunchAttributeProgrammaticStreamSerialization;
    attrs[0].val.programmaticStreamSerializationAllowed = 1;
    cfg.attrs = attrs;
    cfg.numAttrs = 1;

    int nrows_total = B * NPT;
    cudaLaunchKernelEx(&cfg, nrpf_main, points, out, nrows_total);
}